// round 10
// baseline (speedup 1.0000x reference)
#include <cuda_runtime.h>
#include <cuda_bf16.h>

// Haar DWT2: input (8,32,512,512) f32 -> output (8,4,32,256,256) f32
// Subbands: LL, LH, HL, HH (pywt order: LH = highpass along H)
//
// R9: grid-stride over planes. 4096 blocks x 4 iterations; each thread keeps
// its (i, j4) and walks bc -> bc+64 -> bc+128 -> bc+192 (constant pointer
// increments for both input and output, since delta-bc=64 => delta-b=2,
// delta-c=0). Keeps the per-warp LDG queue fed across tile boundaries and
// cuts CTA launch count 4x. Regs capped at 32 via launch_bounds(256,8).

#define H_IN  512
#define W_IN  512
#define H_OUT 256
#define W_OUT 256
#define C_DIM 32
#define B_DIM 8
#define COLS_PER_THREAD 4
#define GROUPS_PER_ROW (W_OUT / COLS_PER_THREAD)   // 64
#define PLANES_PER_THREAD 4
#define BC_STRIDE 64                                // planes between iterations

__global__ __launch_bounds__(256, 8) void haar_dwt2_kernel(
    const float* __restrict__ in, float* __restrict__ out)
{
    unsigned t = blockIdx.x * blockDim.x + threadIdx.x;   // 0 .. 2^20-1
    unsigned j4 = t & (GROUPS_PER_ROW - 1);               // 0..63
    unsigned i  = (t >> 6) & (H_OUT - 1);                 // 0..255
    unsigned bc = t >> 14;                                // 0..63 (first plane)

    // input pointers for first plane
    const float* p0 = in + ((size_t)bc * H_IN + 2u * i) * W_IN + 8u * j4;
    const float* p1 = p0 + W_IN;
    const size_t in_step = (size_t)BC_STRIDE * H_IN * W_IN;     // 64 planes

    // output base for first plane: [B, 4, C, 256, 256]
    unsigned b = bc >> 5;
    unsigned c = bc & 31;
    size_t plane = (size_t)H_OUT * W_OUT;                       // 65536
    size_t sub_stride = (size_t)C_DIM * plane;                  // 2,097,152
    float* obase = out + (((size_t)b * 4) * C_DIM + c) * plane
                 + (size_t)i * W_OUT + 4u * j4;
    // delta-bc = 64 => delta-b = 2, delta-c = 0 => constant output step
    const size_t out_step = (size_t)2 * 4 * C_DIM * plane;      // 2*4*32*65536

#pragma unroll
    for (int it = 0; it < PLANES_PER_THREAD; it++) {
        // front-batch 4 loads (MLP=4), evict-first (read-once stream)
        float4 a0 = __ldcs(reinterpret_cast<const float4*>(p0) + 0);
        float4 a1 = __ldcs(reinterpret_cast<const float4*>(p0) + 1);
        float4 b0 = __ldcs(reinterpret_cast<const float4*>(p1) + 0);
        float4 b1 = __ldcs(reinterpret_cast<const float4*>(p1) + 1);

        float r0[8] = {a0.x, a0.y, a0.z, a0.w, a1.x, a1.y, a1.z, a1.w};
        float r1[8] = {b0.x, b0.y, b0.z, b0.w, b1.x, b1.y, b1.z, b1.w};

        float ll[4], lh[4], hl[4], hh[4];
#pragma unroll
        for (int k = 0; k < 4; k++) {
            float x00 = r0[2*k], x01 = r0[2*k+1];
            float x10 = r1[2*k], x11 = r1[2*k+1];
            float s0 = x00 + x01, s1 = x10 + x11;
            float d0 = x00 - x01, d1 = x10 - x11;
            ll[k] = (s0 + s1) * 0.5f;
            lh[k] = (s0 - s1) * 0.5f;
            hl[k] = (d0 + d1) * 0.5f;
            hh[k] = (d0 - d1) * 0.5f;
        }

        __stcs(reinterpret_cast<float4*>(obase),
               make_float4(ll[0], ll[1], ll[2], ll[3]));
        __stcs(reinterpret_cast<float4*>(obase + sub_stride),
               make_float4(lh[0], lh[1], lh[2], lh[3]));
        __stcs(reinterpret_cast<float4*>(obase + 2 * sub_stride),
               make_float4(hl[0], hl[1], hl[2], hl[3]));
        __stcs(reinterpret_cast<float4*>(obase + 3 * sub_stride),
               make_float4(hh[0], hh[1], hh[2], hh[3]));

        p0 += in_step;
        p1 += in_step;
        obase += out_step;
    }
}

extern "C" void kernel_launch(void* const* d_in, const int* in_sizes, int n_in,
                              void* d_out, int out_size)
{
    const float* in = (const float*)d_in[0];
    float* out = (float*)d_out;
    // total thread-tiles = 8*32*256*64 = 4,194,304; 4 planes/thread
    unsigned total_threads = (B_DIM * C_DIM / PLANES_PER_THREAD)
                           * H_OUT * GROUPS_PER_ROW;            // 1,048,576
    dim3 block(256);
    dim3 grid(total_threads / 256);                             // 4096
    haar_dwt2_kernel<<<grid, block>>>(in, out);
}

// round 11
// speedup vs baseline: 1.0246x; 1.0246x over previous
#include <cuda_runtime.h>
#include <cuda_bf16.h>

// Haar DWT2: input (8,32,512,512) f32 -> output (8,4,32,256,256) f32
// Subbands: LL, LH, HL, HH (pywt order: LH = highpass along H)
//
// R11: R1 geometry (4 output cols/thread — best measured: 74.98us, DRAM 81.4%)
// with 256-bit loads (ld.global.v8.f32, sm_100+): 2x LDG.E.256 per thread
// instead of 4x LDG.E.128. Warp read wavefront: 1KB per LDG. Stores remain
// 128-bit (16B alignment). Cache hints dropped (measured neutral R7/R8).

#define H_IN  512
#define W_IN  512
#define H_OUT 256
#define W_OUT 256
#define C_DIM 32
#define B_DIM 8
#define COLS_PER_THREAD 4
#define GROUPS_PER_ROW (W_OUT / COLS_PER_THREAD)   // 64

__device__ __forceinline__ void ldg256(const float* __restrict__ p,
                                       float4& lo, float4& hi)
{
    asm volatile("ld.global.nc.v8.f32 {%0,%1,%2,%3,%4,%5,%6,%7}, [%8];"
                 : "=f"(lo.x), "=f"(lo.y), "=f"(lo.z), "=f"(lo.w),
                   "=f"(hi.x), "=f"(hi.y), "=f"(hi.z), "=f"(hi.w)
                 : "l"(p));
}

__global__ __launch_bounds__(256) void haar_dwt2_kernel(
    const float* __restrict__ in, float* __restrict__ out)
{
    unsigned t = blockIdx.x * blockDim.x + threadIdx.x;
    // total = B*C * H_OUT * GROUPS_PER_ROW = 8*32*256*64 = 4,194,304
    unsigned j4 = t & (GROUPS_PER_ROW - 1);          // 0..63
    unsigned i  = (t >> 6) & (H_OUT - 1);            // 0..255
    unsigned bc = t >> 14;                           // 0..255  (b*32 + c)

    const float* p0 = in + ((size_t)bc * H_IN + 2u * i) * W_IN + 8u * j4;
    const float* p1 = p0 + W_IN;

    // 2x 256-bit loads, front-batched
    float4 a0, a1, b0, b1;
    ldg256(p0, a0, a1);
    ldg256(p1, b0, b1);

    float r0[8] = {a0.x, a0.y, a0.z, a0.w, a1.x, a1.y, a1.z, a1.w};
    float r1[8] = {b0.x, b0.y, b0.z, b0.w, b1.x, b1.y, b1.z, b1.w};

    float ll[4], lh[4], hl[4], hh[4];
#pragma unroll
    for (int k = 0; k < 4; k++) {
        float x00 = r0[2*k], x01 = r0[2*k+1];
        float x10 = r1[2*k], x11 = r1[2*k+1];
        float s0 = x00 + x01, s1 = x10 + x11;   // row sums
        float d0 = x00 - x01, d1 = x10 - x11;   // row diffs
        ll[k] = (s0 + s1) * 0.5f;
        lh[k] = (s0 - s1) * 0.5f;
        hl[k] = (d0 + d1) * 0.5f;
        hh[k] = (d0 - d1) * 0.5f;
    }

    // output: [B, 4, C, 256, 256]
    unsigned b = bc >> 5;
    unsigned c = bc & 31;
    size_t plane = (size_t)H_OUT * W_OUT;                    // 65536
    size_t base  = (((size_t)b * 4) * C_DIM + c) * plane
                 + (size_t)i * W_OUT + 4u * j4;
    size_t sub_stride = (size_t)C_DIM * plane;

    float4* oLL = reinterpret_cast<float4*>(out + base);
    float4* oLH = reinterpret_cast<float4*>(out + base + sub_stride);
    float4* oHL = reinterpret_cast<float4*>(out + base + 2 * sub_stride);
    float4* oHH = reinterpret_cast<float4*>(out + base + 3 * sub_stride);

    *oLL = make_float4(ll[0], ll[1], ll[2], ll[3]);
    *oLH = make_float4(lh[0], lh[1], lh[2], lh[3]);
    *oHL = make_float4(hl[0], hl[1], hl[2], hl[3]);
    *oHH = make_float4(hh[0], hh[1], hh[2], hh[3]);
}

extern "C" void kernel_launch(void* const* d_in, const int* in_sizes, int n_in,
                              void* d_out, int out_size)
{
    const float* in = (const float*)d_in[0];
    float* out = (float*)d_out;
    unsigned total = B_DIM * C_DIM * H_OUT * GROUPS_PER_ROW;  // 4,194,304
    dim3 block(256);
    dim3 grid(total / 256);
    haar_dwt2_kernel<<<grid, block>>>(in, out);
}

// round 12
// speedup vs baseline: 1.0254x; 1.0008x over previous
#include <cuda_runtime.h>
#include <cuda_bf16.h>

// Haar DWT2: input (8,32,512,512) f32 -> output (8,4,32,256,256) f32
// Subbands: LL, LH, HL, HH (pywt order: LH = highpass along H)
//
// R12: 8 output cols/thread, ALL memory ops 256-bit.
//   Loads : 2 rows x 2x LDG.E.256 = 4 instrs (128B)
//   Stores: 4 subbands x 1x STG.E.256 = 4 instrs (128B), 1KB/warp/subband
// Minimum possible memory-instruction count (8/thread). Tests whether R6's
// regression was L1/issue pressure (fixed here) vs occupancy (not fixed).

#define H_IN  512
#define W_IN  512
#define H_OUT 256
#define W_OUT 256
#define C_DIM 32
#define B_DIM 8
#define COLS_PER_THREAD 8
#define GROUPS_PER_ROW (W_OUT / COLS_PER_THREAD)   // 32

__device__ __forceinline__ void ldg256(const float* __restrict__ p,
                                       float4& lo, float4& hi)
{
    asm volatile("ld.global.nc.v8.f32 {%0,%1,%2,%3,%4,%5,%6,%7}, [%8];"
                 : "=f"(lo.x), "=f"(lo.y), "=f"(lo.z), "=f"(lo.w),
                   "=f"(hi.x), "=f"(hi.y), "=f"(hi.z), "=f"(hi.w)
                 : "l"(p));
}

__device__ __forceinline__ void stg256(float* __restrict__ p,
                                       const float4& lo, const float4& hi)
{
    asm volatile("st.global.v8.f32 [%0], {%1,%2,%3,%4,%5,%6,%7,%8};"
                 :: "l"(p),
                    "f"(lo.x), "f"(lo.y), "f"(lo.z), "f"(lo.w),
                    "f"(hi.x), "f"(hi.y), "f"(hi.z), "f"(hi.w)
                 : "memory");
}

__global__ __launch_bounds__(256) void haar_dwt2_kernel(
    const float* __restrict__ in, float* __restrict__ out)
{
    unsigned t = blockIdx.x * blockDim.x + threadIdx.x;
    // total = B*C * H_OUT * GROUPS_PER_ROW = 8*32*256*32 = 2,097,152
    unsigned j8 = t & (GROUPS_PER_ROW - 1);          // 0..31
    unsigned i  = (t >> 5) & (H_OUT - 1);            // 0..255
    unsigned bc = t >> 13;                           // 0..255  (b*32 + c)

    const float* p0 = in + ((size_t)bc * H_IN + 2u * i) * W_IN + 16u * j8;
    const float* p1 = p0 + W_IN;

    // 4x 256-bit loads, front-batched (MLP=4 wide ops = 128B in flight)
    float4 a0, a1, a2, a3, b0, b1, b2, b3;
    ldg256(p0,      a0, a1);
    ldg256(p0 + 8,  a2, a3);
    ldg256(p1,      b0, b1);
    ldg256(p1 + 8,  b2, b3);

    float r0[16] = {a0.x,a0.y,a0.z,a0.w, a1.x,a1.y,a1.z,a1.w,
                    a2.x,a2.y,a2.z,a2.w, a3.x,a3.y,a3.z,a3.w};
    float r1[16] = {b0.x,b0.y,b0.z,b0.w, b1.x,b1.y,b1.z,b1.w,
                    b2.x,b2.y,b2.z,b2.w, b3.x,b3.y,b3.z,b3.w};

    float ll[8], lh[8], hl[8], hh[8];
#pragma unroll
    for (int k = 0; k < 8; k++) {
        float x00 = r0[2*k], x01 = r0[2*k+1];
        float x10 = r1[2*k], x11 = r1[2*k+1];
        float s0 = x00 + x01, s1 = x10 + x11;
        float d0 = x00 - x01, d1 = x10 - x11;
        ll[k] = (s0 + s1) * 0.5f;
        lh[k] = (s0 - s1) * 0.5f;
        hl[k] = (d0 + d1) * 0.5f;
        hh[k] = (d0 - d1) * 0.5f;
    }

    // output: [B, 4, C, 256, 256]
    unsigned b = bc >> 5;
    unsigned c = bc & 31;
    size_t plane = (size_t)H_OUT * W_OUT;                    // 65536
    size_t base  = (((size_t)b * 4) * C_DIM + c) * plane
                 + (size_t)i * W_OUT + 8u * j8;              // 32B-aligned
    size_t sub_stride = (size_t)C_DIM * plane;

    stg256(out + base,
           make_float4(ll[0], ll[1], ll[2], ll[3]),
           make_float4(ll[4], ll[5], ll[6], ll[7]));
    stg256(out + base + sub_stride,
           make_float4(lh[0], lh[1], lh[2], lh[3]),
           make_float4(lh[4], lh[5], lh[6], lh[7]));
    stg256(out + base + 2 * sub_stride,
           make_float4(hl[0], hl[1], hl[2], hl[3]),
           make_float4(hl[4], hl[5], hl[6], hl[7]));
    stg256(out + base + 3 * sub_stride,
           make_float4(hh[0], hh[1], hh[2], hh[3]),
           make_float4(hh[4], hh[5], hh[6], hh[7]));
}

extern "C" void kernel_launch(void* const* d_in, const int* in_sizes, int n_in,
                              void* d_out, int out_size)
{
    const float* in = (const float*)d_in[0];
    float* out = (float*)d_out;
    unsigned total = B_DIM * C_DIM * H_OUT * GROUPS_PER_ROW;  // 2,097,152
    dim3 block(256);
    dim3 grid(total / 256);                                   // 8192
    haar_dwt2_kernel<<<grid, block>>>(in, out);
}